// round 3
// baseline (speedup 1.0000x reference)
#include <cuda_runtime.h>
#include <cuda_fp16.h>

// Problem constants (match reference)
#define NN       150000        // total nodes (users + items)
#define DIM      64
#define NE       4800000       // edges
#define NB       147           // ceil(NN / 1024)

// ---------------- scratch (device globals; no allocation allowed) ------------
__device__ int    g_cnt[NN];
__device__ int    g_rowptr[NN + 1];
__device__ int    g_cursor[NN];
__device__ int    g_bsum[NB];
__device__ int2   g_edge[NE];                 // packed {col, float_as_int(val)}
__device__ __half g_h0[(size_t)NN * DIM];     // emb_h
__device__ __half g_h1[(size_t)NN * DIM];     // y1
__device__ __half g_h2[(size_t)NN * DIM];     // y2
__device__ __half g_h3[(size_t)NN * DIM];     // y3

// ---------------- CSR build ---------------------------------------------------
__global__ void k_zero_cnt() {
    int i = blockIdx.x * blockDim.x + threadIdx.x;
    for (; i < NN; i += gridDim.x * blockDim.x) g_cnt[i] = 0;
}

__global__ void k_hist(const int4* __restrict__ rows4) {
    int i = blockIdx.x * blockDim.x + threadIdx.x;
    const int n4 = NE / 4;
    for (; i < n4; i += gridDim.x * blockDim.x) {
        int4 r = rows4[i];
        atomicAdd(&g_cnt[r.x], 1);
        atomicAdd(&g_cnt[r.y], 1);
        atomicAdd(&g_cnt[r.z], 1);
        atomicAdd(&g_cnt[r.w], 1);
    }
}

__global__ void k_chunksum() {
    __shared__ int sh[256];
    int b = blockIdx.x, t = threadIdx.x;
    int base = b * 1024;
    int s = 0;
    #pragma unroll
    for (int k = 0; k < 4; k++) {
        int i = base + t + k * 256;
        if (i < NN) s += g_cnt[i];
    }
    sh[t] = s;
    __syncthreads();
    for (int off = 128; off > 0; off >>= 1) {
        if (t < off) sh[t] += sh[t + off];
        __syncthreads();
    }
    if (t == 0) g_bsum[b] = sh[0];
}

__global__ void k_scan_bsum() {
    __shared__ int sh[256];
    int t = threadIdx.x;
    int v = (t < NB) ? g_bsum[t] : 0;
    sh[t] = v;
    __syncthreads();
    for (int off = 1; off < 256; off <<= 1) {
        int add = (t >= off) ? sh[t - off] : 0;
        __syncthreads();
        sh[t] += add;
        __syncthreads();
    }
    if (t < NB) g_bsum[t] = sh[t] - v;   // exclusive
}

__global__ void k_writeptr() {
    __shared__ int sh[1024];
    int b = blockIdx.x, t = threadIdx.x;
    int i = b * 1024 + t;
    int v = (i < NN) ? g_cnt[i] : 0;
    sh[t] = v;
    __syncthreads();
    for (int off = 1; off < 1024; off <<= 1) {
        int add = (t >= off) ? sh[t - off] : 0;
        __syncthreads();
        sh[t] += add;
        __syncthreads();
    }
    int incl = sh[t];
    if (i < NN) {
        int rp = g_bsum[b] + (incl - v);
        g_rowptr[i] = rp;
        g_cursor[i] = rp;
        if (i == NN - 1) g_rowptr[NN] = g_bsum[b] + incl;   // == NE
    }
}

__global__ void k_scatter(const int4* __restrict__ rows4,
                          const int4* __restrict__ cols4,
                          const float4* __restrict__ vals4) {
    int i = blockIdx.x * blockDim.x + threadIdx.x;
    const int n4 = NE / 4;
    for (; i < n4; i += gridDim.x * blockDim.x) {
        int4   r = rows4[i];
        int4   c = cols4[i];
        float4 v = vals4[i];
        int p0 = atomicAdd(&g_cursor[r.x], 1);
        int p1 = atomicAdd(&g_cursor[r.y], 1);
        int p2 = atomicAdd(&g_cursor[r.z], 1);
        int p3 = atomicAdd(&g_cursor[r.w], 1);
        g_edge[p0] = make_int2(c.x, __float_as_int(v.x));
        g_edge[p1] = make_int2(c.y, __float_as_int(v.y));
        g_edge[p2] = make_int2(c.z, __float_as_int(v.z));
        g_edge[p3] = make_int2(c.w, __float_as_int(v.w));
    }
}

// ---------------- emb fp32 -> fp16 conversion --------------------------------
__global__ void k_conv_emb(const float* __restrict__ emb) {
    int i = blockIdx.x * blockDim.x + threadIdx.x;
    const int total4 = (NN * DIM) / 4;
    for (; i < total4; i += gridDim.x * blockDim.x) {
        float4 f = *reinterpret_cast<const float4*>(&emb[(size_t)i * 4]);
        __half2 h0 = __floats2half2_rn(f.x, f.y);
        __half2 h1 = __floats2half2_rn(f.z, f.w);
        *reinterpret_cast<__half2*>(&g_h0[(size_t)i * 4])     = h0;
        *reinterpret_cast<__half2*>(&g_h0[(size_t)i * 4 + 2]) = h1;
    }
}

// ---------------- SpMM layer: warp-per-row, 2 edges per iteration -------------
// Lane layout: half = lane>>4 (edge slot), q = lane&15 owns dims [4q, 4q+4).
// y[row] = sum_e val_e * x[col_e]   (fp16 in, fp32 accum, fp16 out)
__global__ void __launch_bounds__(256)
k_spmm(const __half* __restrict__ xin, __half* __restrict__ yout) {
    int gw = (blockIdx.x * blockDim.x + threadIdx.x) >> 5;
    if (gw >= NN) return;
    int lane = threadIdx.x & 31;
    int q    = lane & 15;
    int hsel = lane & 16;          // 0 lower half, 16 upper half

    int s = g_rowptr[gw];
    int e = g_rowptr[gw + 1];

    float4 acc = make_float4(0.f, 0.f, 0.f, 0.f);
    int base = s;

    // full 32-edge chunks: 16 iterations, 2 edges each
    for (; base + 32 <= e; base += 32) {
        int2 ed = g_edge[base + lane];
        #pragma unroll
        for (int j = 0; j < 16; j++) {
            int src = j + hsel;
            int   c = __shfl_sync(0xffffffffu, ed.x, src);
            float v = __int_as_float(__shfl_sync(0xffffffffu, ed.y, src));
            uint2 r = *reinterpret_cast<const uint2*>(
                &xin[(size_t)c * DIM + q * 4]);
            float2 f0 = __half22float2(*reinterpret_cast<__half2*>(&r.x));
            float2 f1 = __half22float2(*reinterpret_cast<__half2*>(&r.y));
            acc.x = fmaf(v, f0.x, acc.x);
            acc.y = fmaf(v, f0.y, acc.y);
            acc.z = fmaf(v, f1.x, acc.z);
            acc.w = fmaf(v, f1.y, acc.w);
        }
    }
    // remainder (zero-padded dummy edges: col 0 / val 0 -> harmless hot-line loads)
    int rem = e - base;
    if (rem > 0) {
        int2 ed = (lane < rem) ? g_edge[base + lane] : make_int2(0, 0);
        int jcap = rem > 16 ? 16 : rem;
        for (int j = 0; j < jcap; j++) {
            int src = j + hsel;
            int   c = __shfl_sync(0xffffffffu, ed.x, src);
            float v = __int_as_float(__shfl_sync(0xffffffffu, ed.y, src));
            uint2 r = *reinterpret_cast<const uint2*>(
                &xin[(size_t)c * DIM + q * 4]);
            float2 f0 = __half22float2(*reinterpret_cast<__half2*>(&r.x));
            float2 f1 = __half22float2(*reinterpret_cast<__half2*>(&r.y));
            acc.x = fmaf(v, f0.x, acc.x);
            acc.y = fmaf(v, f0.y, acc.y);
            acc.z = fmaf(v, f1.x, acc.z);
            acc.w = fmaf(v, f1.y, acc.w);
        }
    }

    // combine the two half-warp partial sums
    acc.x += __shfl_xor_sync(0xffffffffu, acc.x, 16);
    acc.y += __shfl_xor_sync(0xffffffffu, acc.y, 16);
    acc.z += __shfl_xor_sync(0xffffffffu, acc.z, 16);
    acc.w += __shfl_xor_sync(0xffffffffu, acc.w, 16);

    if (lane < 16) {
        __half2 a = __floats2half2_rn(acc.x, acc.y);
        __half2 b = __floats2half2_rn(acc.z, acc.w);
        uint2 pk;
        pk.x = *reinterpret_cast<unsigned*>(&a);
        pk.y = *reinterpret_cast<unsigned*>(&b);
        *reinterpret_cast<uint2*>(&yout[(size_t)gw * DIM + q * 4]) = pk;
    }
}

// ---------------- final combine: out = emb + y1/2 + y2/3 + y3/4 ---------------
__global__ void k_combine(const float* __restrict__ emb, float* __restrict__ out) {
    int i = blockIdx.x * blockDim.x + threadIdx.x;
    const int total4 = (NN * DIM) / 4;
    if (i >= total4) return;

    float4 ef = *reinterpret_cast<const float4*>(&emb[(size_t)i * 4]);
    uint2 a = *reinterpret_cast<const uint2*>(&g_h1[(size_t)i * 4]);
    uint2 b = *reinterpret_cast<const uint2*>(&g_h2[(size_t)i * 4]);
    uint2 c = *reinterpret_cast<const uint2*>(&g_h3[(size_t)i * 4]);

    float2 a0 = __half22float2(*reinterpret_cast<__half2*>(&a.x));
    float2 a1 = __half22float2(*reinterpret_cast<__half2*>(&a.y));
    float2 b0 = __half22float2(*reinterpret_cast<__half2*>(&b.x));
    float2 b1 = __half22float2(*reinterpret_cast<__half2*>(&b.y));
    float2 c0 = __half22float2(*reinterpret_cast<__half2*>(&c.x));
    float2 c1 = __half22float2(*reinterpret_cast<__half2*>(&c.y));

    const float w1 = 1.0f / 2.0f, w2 = 1.0f / 3.0f, w3 = 1.0f / 4.0f;
    ef.x = ef.x + w1 * a0.x + w2 * b0.x + w3 * c0.x;
    ef.y = ef.y + w1 * a0.y + w2 * b0.y + w3 * c0.y;
    ef.z = ef.z + w1 * a1.x + w2 * b1.x + w3 * c1.x;
    ef.w = ef.w + w1 * a1.y + w2 * b1.y + w3 * c1.y;

    *reinterpret_cast<float4*>(&out[(size_t)i * 4]) = ef;
}

// ---------------- launch ------------------------------------------------------
extern "C" void kernel_launch(void* const* d_in, const int* in_sizes, int n_in,
                              void* d_out, int out_size) {
    const int*   rows = (const int*)d_in[0];
    const int*   cols = (const int*)d_in[1];
    const float* vals = (const float*)d_in[2];
    const float* emb  = (const float*)d_in[3];
    float*       out  = (float*)d_out;

    (void)in_sizes; (void)n_in; (void)out_size;

    static __half* h0 = nullptr;
    static __half* h1 = nullptr;
    static __half* h2 = nullptr;
    static __half* h3 = nullptr;
    if (!h0) {
        void* p;
        cudaGetSymbolAddress(&p, g_h0); h0 = (__half*)p;
        cudaGetSymbolAddress(&p, g_h1); h1 = (__half*)p;
        cudaGetSymbolAddress(&p, g_h2); h2 = (__half*)p;
        cudaGetSymbolAddress(&p, g_h3); h3 = (__half*)p;
    }

    // ---- CSR build + emb conversion ----
    k_zero_cnt<<<256, 256>>>();
    k_conv_emb<<<2048, 256>>>(emb);
    k_hist<<<2048, 256>>>((const int4*)rows);
    k_chunksum<<<NB, 256>>>();
    k_scan_bsum<<<1, 256>>>();
    k_writeptr<<<NB, 1024>>>();
    k_scatter<<<2048, 256>>>((const int4*)rows, (const int4*)cols,
                             (const float4*)vals);

    // ---- 3 SpMM layers ----
    const int threads = 256;
    const int blocks  = (NN * 32 + threads - 1) / threads;  // warp per row

    k_spmm<<<blocks, threads>>>(h0, h1);   // y1 = A @ emb
    k_spmm<<<blocks, threads>>>(h1, h2);   // y2 = A @ y1
    k_spmm<<<blocks, threads>>>(h2, h3);   // y3 = A @ y2

    // ---- out = emb + y1/2 + y2/3 + y3/4 ----
    const int total4 = (NN * DIM) / 4;
    k_combine<<<(total4 + 255) / 256, 256>>>(emb, out);
}

// round 4
// speedup vs baseline: 1.4208x; 1.4208x over previous
#include <cuda_runtime.h>
#include <cuda_fp16.h>

// Problem constants (match reference)
#define NN       150000        // total nodes (users + items)
#define DIM      64
#define NE       4800000       // edges
#define NB       147           // ceil(NN / 1024)

// ---------------- scratch (device globals; no allocation allowed) ------------
__device__ int    g_cnt[NN];
__device__ int    g_rowptr[NN + 1];
__device__ int    g_cursor[NN];
__device__ int    g_bsum[NB];
__device__ int2   g_edge[NE];                 // packed {col, float_as_int(val)}
__device__ __half g_h0[(size_t)NN * DIM];     // emb_h
__device__ __half g_h1[(size_t)NN * DIM];     // y1
__device__ __half g_h2[(size_t)NN * DIM];     // y2
__device__ __half g_h3[(size_t)NN * DIM];     // y3

// ---------------- emb fp32 -> fp16 conversion, fused with cnt zeroing ---------
__global__ void k_conv_zero(const float* __restrict__ emb) {
    int i = blockIdx.x * blockDim.x + threadIdx.x;
    const int stride = gridDim.x * blockDim.x;

    // zero the histogram counters (first portion of the grid-stride range)
    for (int z = i; z < NN; z += stride) g_cnt[z] = 0;

    // convert embeddings
    const int total4 = (NN * DIM) / 4;
    for (int t = i; t < total4; t += stride) {
        float4 f = *reinterpret_cast<const float4*>(&emb[(size_t)t * 4]);
        __half2 h0 = __floats2half2_rn(f.x, f.y);
        __half2 h1 = __floats2half2_rn(f.z, f.w);
        *reinterpret_cast<__half2*>(&g_h0[(size_t)t * 4])     = h0;
        *reinterpret_cast<__half2*>(&g_h0[(size_t)t * 4 + 2]) = h1;
    }
}

// ---------------- CSR build ---------------------------------------------------
__global__ void k_hist(const int4* __restrict__ rows4) {
    int i = blockIdx.x * blockDim.x + threadIdx.x;
    const int n8 = NE / 8;   // process 8 edges (2×int4) per iteration
    for (; i < n8; i += gridDim.x * blockDim.x) {
        int4 a = rows4[i * 2];
        int4 b = rows4[i * 2 + 1];
        atomicAdd(&g_cnt[a.x], 1);
        atomicAdd(&g_cnt[a.y], 1);
        atomicAdd(&g_cnt[a.z], 1);
        atomicAdd(&g_cnt[a.w], 1);
        atomicAdd(&g_cnt[b.x], 1);
        atomicAdd(&g_cnt[b.y], 1);
        atomicAdd(&g_cnt[b.z], 1);
        atomicAdd(&g_cnt[b.w], 1);
    }
}

__global__ void k_chunksum() {
    __shared__ int sh[256];
    int b = blockIdx.x, t = threadIdx.x;
    int base = b * 1024;
    int s = 0;
    #pragma unroll
    for (int k = 0; k < 4; k++) {
        int i = base + t + k * 256;
        if (i < NN) s += g_cnt[i];
    }
    sh[t] = s;
    __syncthreads();
    for (int off = 128; off > 0; off >>= 1) {
        if (t < off) sh[t] += sh[t + off];
        __syncthreads();
    }
    if (t == 0) g_bsum[b] = sh[0];
}

__global__ void k_scan_bsum() {
    __shared__ int sh[256];
    int t = threadIdx.x;
    int v = (t < NB) ? g_bsum[t] : 0;
    sh[t] = v;
    __syncthreads();
    for (int off = 1; off < 256; off <<= 1) {
        int add = (t >= off) ? sh[t - off] : 0;
        __syncthreads();
        sh[t] += add;
        __syncthreads();
    }
    if (t < NB) g_bsum[t] = sh[t] - v;   // exclusive
}

__global__ void k_writeptr() {
    __shared__ int sh[1024];
    int b = blockIdx.x, t = threadIdx.x;
    int i = b * 1024 + t;
    int v = (i < NN) ? g_cnt[i] : 0;
    sh[t] = v;
    __syncthreads();
    for (int off = 1; off < 1024; off <<= 1) {
        int add = (t >= off) ? sh[t - off] : 0;
        __syncthreads();
        sh[t] += add;
        __syncthreads();
    }
    int incl = sh[t];
    if (i < NN) {
        int rp = g_bsum[b] + (incl - v);
        g_rowptr[i] = rp;
        g_cursor[i] = rp;
        if (i == NN - 1) g_rowptr[NN] = g_bsum[b] + incl;   // == NE
    }
}

__global__ void k_scatter(const int4* __restrict__ rows4,
                          const int4* __restrict__ cols4,
                          const float4* __restrict__ vals4) {
    int i = blockIdx.x * blockDim.x + threadIdx.x;
    const int n8 = NE / 8;
    for (; i < n8; i += gridDim.x * blockDim.x) {
        int4   ra = rows4[i * 2];
        int4   rb = rows4[i * 2 + 1];
        int4   ca = cols4[i * 2];
        int4   cb = cols4[i * 2 + 1];
        float4 va = vals4[i * 2];
        float4 vb = vals4[i * 2 + 1];
        int p0 = atomicAdd(&g_cursor[ra.x], 1);
        int p1 = atomicAdd(&g_cursor[ra.y], 1);
        int p2 = atomicAdd(&g_cursor[ra.z], 1);
        int p3 = atomicAdd(&g_cursor[ra.w], 1);
        int p4 = atomicAdd(&g_cursor[rb.x], 1);
        int p5 = atomicAdd(&g_cursor[rb.y], 1);
        int p6 = atomicAdd(&g_cursor[rb.z], 1);
        int p7 = atomicAdd(&g_cursor[rb.w], 1);
        g_edge[p0] = make_int2(ca.x, __float_as_int(va.x));
        g_edge[p1] = make_int2(ca.y, __float_as_int(va.y));
        g_edge[p2] = make_int2(ca.z, __float_as_int(va.z));
        g_edge[p3] = make_int2(ca.w, __float_as_int(va.w));
        g_edge[p4] = make_int2(cb.x, __float_as_int(vb.x));
        g_edge[p5] = make_int2(cb.y, __float_as_int(vb.y));
        g_edge[p6] = make_int2(cb.z, __float_as_int(vb.z));
        g_edge[p7] = make_int2(cb.w, __float_as_int(vb.w));
    }
}

// ---------------- SpMM layer: warp-per-row, uniform edge LDG (no shfl) --------
// Each lane owns dims [2*lane, 2*lane+2). Edge (col,val) read by ALL lanes with
// the same address: 1 wavefront, L1-resident line after first touch.
__global__ void __launch_bounds__(256)
k_spmm(const __half* __restrict__ xin, __half* __restrict__ yout) {
    int gw = (blockIdx.x * blockDim.x + threadIdx.x) >> 5;
    if (gw >= NN) return;
    int lane = threadIdx.x & 31;

    int s = g_rowptr[gw];
    int e = g_rowptr[gw + 1];

    const __half* xl = xin + lane * 2;      // lane's column slice base
    float2 acc = make_float2(0.f, 0.f);
    int base = s;

    // full 32-edge chunks, fully unrolled: independent uniform LDG.64 per edge
    for (; base + 32 <= e; base += 32) {
        #pragma unroll
        for (int j = 0; j < 32; j++) {
            int2 ev = __ldg(&g_edge[base + j]);
            float v = __int_as_float(ev.y);
            __half2 hv = *reinterpret_cast<const __half2*>(xl + (size_t)ev.x * DIM);
            float2 xv = __half22float2(hv);
            acc.x = fmaf(v, xv.x, acc.x);
            acc.y = fmaf(v, xv.y, acc.y);
        }
    }
    // remainder
    for (int j = base; j < e; j++) {
        int2 ev = __ldg(&g_edge[j]);
        float v = __int_as_float(ev.y);
        __half2 hv = *reinterpret_cast<const __half2*>(xl + (size_t)ev.x * DIM);
        float2 xv = __half22float2(hv);
        acc.x = fmaf(v, xv.x, acc.x);
        acc.y = fmaf(v, xv.y, acc.y);
    }

    *reinterpret_cast<__half2*>(&yout[(size_t)gw * DIM + lane * 2]) =
        __floats2half2_rn(acc.x, acc.y);
}

// ---------------- final combine: out = emb + y1/2 + y2/3 + y3/4 ---------------
__global__ void k_combine(const float* __restrict__ emb, float* __restrict__ out) {
    int i = blockIdx.x * blockDim.x + threadIdx.x;
    const int total4 = (NN * DIM) / 4;
    if (i >= total4) return;

    float4 ef = *reinterpret_cast<const float4*>(&emb[(size_t)i * 4]);
    uint2 a = *reinterpret_cast<const uint2*>(&g_h1[(size_t)i * 4]);
    uint2 b = *reinterpret_cast<const uint2*>(&g_h2[(size_t)i * 4]);
    uint2 c = *reinterpret_cast<const uint2*>(&g_h3[(size_t)i * 4]);

    float2 a0 = __half22float2(*reinterpret_cast<__half2*>(&a.x));
    float2 a1 = __half22float2(*reinterpret_cast<__half2*>(&a.y));
    float2 b0 = __half22float2(*reinterpret_cast<__half2*>(&b.x));
    float2 b1 = __half22float2(*reinterpret_cast<__half2*>(&b.y));
    float2 c0 = __half22float2(*reinterpret_cast<__half2*>(&c.x));
    float2 c1 = __half22float2(*reinterpret_cast<__half2*>(&c.y));

    const float w1 = 1.0f / 2.0f, w2 = 1.0f / 3.0f, w3 = 1.0f / 4.0f;
    ef.x = ef.x + w1 * a0.x + w2 * b0.x + w3 * c0.x;
    ef.y = ef.y + w1 * a0.y + w2 * b0.y + w3 * c0.y;
    ef.z = ef.z + w1 * a1.x + w2 * b1.x + w3 * c1.x;
    ef.w = ef.w + w1 * a1.y + w2 * b1.y + w3 * c1.y;

    *reinterpret_cast<float4*>(&out[(size_t)i * 4]) = ef;
}

// ---------------- launch ------------------------------------------------------
extern "C" void kernel_launch(void* const* d_in, const int* in_sizes, int n_in,
                              void* d_out, int out_size) {
    const int*   rows = (const int*)d_in[0];
    const int*   cols = (const int*)d_in[1];
    const float* vals = (const float*)d_in[2];
    const float* emb  = (const float*)d_in[3];
    float*       out  = (float*)d_out;

    (void)in_sizes; (void)n_in; (void)out_size;

    static __half* h0 = nullptr;
    static __half* h1 = nullptr;
    static __half* h2 = nullptr;
    static __half* h3 = nullptr;
    if (!h0) {
        void* p;
        cudaGetSymbolAddress(&p, g_h0); h0 = (__half*)p;
        cudaGetSymbolAddress(&p, g_h1); h1 = (__half*)p;
        cudaGetSymbolAddress(&p, g_h2); h2 = (__half*)p;
        cudaGetSymbolAddress(&p, g_h3); h3 = (__half*)p;
    }

    // ---- CSR build + emb conversion ----
    k_conv_zero<<<2048, 256>>>(emb);
    k_hist<<<1280, 256>>>((const int4*)rows);
    k_chunksum<<<NB, 256>>>();
    k_scan_bsum<<<1, 256>>>();
    k_writeptr<<<NB, 1024>>>();
    k_scatter<<<1280, 256>>>((const int4*)rows, (const int4*)cols,
                             (const float4*)vals);

    // ---- 3 SpMM layers ----
    const int threads = 256;
    const int blocks  = (NN * 32 + threads - 1) / threads;  // warp per row

    k_spmm<<<blocks, threads>>>(h0, h1);   // y1 = A @ emb
    k_spmm<<<blocks, threads>>>(h1, h2);   // y2 = A @ y1
    k_spmm<<<blocks, threads>>>(h2, h3);   // y3 = A @ y2

    // ---- out = emb + y1/2 + y2/3 + y3/4 ----
    const int total4 = (NN * DIM) / 4;
    k_combine<<<(total4 + 255) / 256, 256>>>(emb, out);
}

// round 5
// speedup vs baseline: 1.5684x; 1.1039x over previous
#include <cuda_runtime.h>
#include <cuda_fp16.h>

// Problem constants (match reference)
#define NN       150000        // total nodes (users + items)
#define DIM      64
#define NE       4800000       // edges
#define NB       147           // ceil(NN / 1024)

// ---------------- scratch (device globals; no allocation allowed) ------------
__device__ int    g_cnt[NN];
__device__ int    g_rowptr[NN + 1];
__device__ int    g_cursor[NN];
__device__ int    g_bsum[NB];
__device__ int2   g_edge[NE];                 // packed {col, float_as_int(val)}
__device__ __half g_h0[(size_t)NN * DIM];     // emb_h
__device__ __half g_h1[(size_t)NN * DIM];     // y1
__device__ __half g_h2[(size_t)NN * DIM];     // y2
__device__ __half g_h3[(size_t)NN * DIM];     // y3

// ---------------- emb fp32 -> fp16 conversion, fused with cnt zeroing ---------
__global__ void k_conv_zero(const float* __restrict__ emb) {
    int i = blockIdx.x * blockDim.x + threadIdx.x;
    const int stride = gridDim.x * blockDim.x;

    for (int z = i; z < NN; z += stride) g_cnt[z] = 0;

    const int total4 = (NN * DIM) / 4;
    for (int t = i; t < total4; t += stride) {
        float4 f = *reinterpret_cast<const float4*>(&emb[(size_t)t * 4]);
        __half2 h0 = __floats2half2_rn(f.x, f.y);
        __half2 h1 = __floats2half2_rn(f.z, f.w);
        *reinterpret_cast<__half2*>(&g_h0[(size_t)t * 4])     = h0;
        *reinterpret_cast<__half2*>(&g_h0[(size_t)t * 4 + 2]) = h1;
    }
}

// ---------------- CSR build ---------------------------------------------------
__global__ void k_hist(const int4* __restrict__ rows4) {
    int i = blockIdx.x * blockDim.x + threadIdx.x;
    const int n8 = NE / 8;
    for (; i < n8; i += gridDim.x * blockDim.x) {
        int4 a = rows4[i * 2];
        int4 b = rows4[i * 2 + 1];
        atomicAdd(&g_cnt[a.x], 1);
        atomicAdd(&g_cnt[a.y], 1);
        atomicAdd(&g_cnt[a.z], 1);
        atomicAdd(&g_cnt[a.w], 1);
        atomicAdd(&g_cnt[b.x], 1);
        atomicAdd(&g_cnt[b.y], 1);
        atomicAdd(&g_cnt[b.z], 1);
        atomicAdd(&g_cnt[b.w], 1);
    }
}

__global__ void k_chunksum() {
    __shared__ int sh[256];
    int b = blockIdx.x, t = threadIdx.x;
    int base = b * 1024;
    int s = 0;
    #pragma unroll
    for (int k = 0; k < 4; k++) {
        int i = base + t + k * 256;
        if (i < NN) s += g_cnt[i];
    }
    sh[t] = s;
    __syncthreads();
    for (int off = 128; off > 0; off >>= 1) {
        if (t < off) sh[t] += sh[t + off];
        __syncthreads();
    }
    if (t == 0) g_bsum[b] = sh[0];
}

__global__ void k_scan_bsum() {
    __shared__ int sh[256];
    int t = threadIdx.x;
    int v = (t < NB) ? g_bsum[t] : 0;
    sh[t] = v;
    __syncthreads();
    for (int off = 1; off < 256; off <<= 1) {
        int add = (t >= off) ? sh[t - off] : 0;
        __syncthreads();
        sh[t] += add;
        __syncthreads();
    }
    if (t < NB) g_bsum[t] = sh[t] - v;   // exclusive
}

__global__ void k_writeptr() {
    __shared__ int sh[1024];
    int b = blockIdx.x, t = threadIdx.x;
    int i = b * 1024 + t;
    int v = (i < NN) ? g_cnt[i] : 0;
    sh[t] = v;
    __syncthreads();
    for (int off = 1; off < 1024; off <<= 1) {
        int add = (t >= off) ? sh[t - off] : 0;
        __syncthreads();
        sh[t] += add;
        __syncthreads();
    }
    int incl = sh[t];
    if (i < NN) {
        int rp = g_bsum[b] + (incl - v);
        g_rowptr[i] = rp;
        g_cursor[i] = rp;
        if (i == NN - 1) g_rowptr[NN] = g_bsum[b] + incl;   // == NE
    }
}

__global__ void k_scatter(const int4* __restrict__ rows4,
                          const int4* __restrict__ cols4,
                          const float4* __restrict__ vals4) {
    int i = blockIdx.x * blockDim.x + threadIdx.x;
    const int n8 = NE / 8;
    for (; i < n8; i += gridDim.x * blockDim.x) {
        int4   ra = rows4[i * 2];
        int4   rb = rows4[i * 2 + 1];
        int4   ca = cols4[i * 2];
        int4   cb = cols4[i * 2 + 1];
        float4 va = vals4[i * 2];
        float4 vb = vals4[i * 2 + 1];
        int p0 = atomicAdd(&g_cursor[ra.x], 1);
        int p1 = atomicAdd(&g_cursor[ra.y], 1);
        int p2 = atomicAdd(&g_cursor[ra.z], 1);
        int p3 = atomicAdd(&g_cursor[ra.w], 1);
        int p4 = atomicAdd(&g_cursor[rb.x], 1);
        int p5 = atomicAdd(&g_cursor[rb.y], 1);
        int p6 = atomicAdd(&g_cursor[rb.z], 1);
        int p7 = atomicAdd(&g_cursor[rb.w], 1);
        g_edge[p0] = make_int2(ca.x, __float_as_int(va.x));
        g_edge[p1] = make_int2(ca.y, __float_as_int(va.y));
        g_edge[p2] = make_int2(ca.z, __float_as_int(va.z));
        g_edge[p3] = make_int2(ca.w, __float_as_int(va.w));
        g_edge[p4] = make_int2(cb.x, __float_as_int(vb.x));
        g_edge[p5] = make_int2(cb.y, __float_as_int(vb.y));
        g_edge[p6] = make_int2(cb.z, __float_as_int(vb.z));
        g_edge[p7] = make_int2(cb.w, __float_as_int(vb.w));
    }
}

// ---------------- SpMM layer: warp-per-row, 2 edges/iter, 1 LDG each ----------
// q = lane&15 owns dims [4q,4q+4) as uint2; hsel = lane>>4 selects edge of pair.
// Per iteration: 1 edge LDG.64 (2 adjacent int2 -> 1 line, broadcast within
// halves) + 1 gather LDG.64 (one 128B row-line per half). No shfl in the loop.
__global__ void __launch_bounds__(256)
k_spmm(const __half* __restrict__ xin, __half* __restrict__ yout) {
    int gw = (blockIdx.x * blockDim.x + threadIdx.x) >> 5;
    if (gw >= NN) return;
    int lane = threadIdx.x & 31;
    int q    = lane & 15;
    int hsel = lane >> 4;               // 0 or 1: which edge of the pair

    int s = __ldg(&g_rowptr[gw]);
    int e = __ldg(&g_rowptr[gw + 1]);

    const __half* xq = xin + q * 4;     // lane's dim-slice base
    float4 acc = make_float4(0.f, 0.f, 0.f, 0.f);
    int base = s;

    // full 32-edge chunks: 16 iterations x 2 edges
    for (; base + 32 <= e; base += 32) {
        #pragma unroll
        for (int j = 0; j < 16; j++) {
            int2 ev = __ldg(&g_edge[base + 2 * j + hsel]);
            float v = __int_as_float(ev.y);
            uint2 r = *reinterpret_cast<const uint2*>(xq + (size_t)ev.x * DIM);
            float2 f0 = __half22float2(*reinterpret_cast<__half2*>(&r.x));
            float2 f1 = __half22float2(*reinterpret_cast<__half2*>(&r.y));
            acc.x = fmaf(v, f0.x, acc.x);
            acc.y = fmaf(v, f0.y, acc.y);
            acc.z = fmaf(v, f1.x, acc.z);
            acc.w = fmaf(v, f1.y, acc.w);
        }
    }
    // remainder: pairs, dummy (col 0, val 0) for the odd tail
    for (int j = base; j < e; j += 2) {
        int idx = j + hsel;
        int2 ev = (idx < e) ? __ldg(&g_edge[idx]) : make_int2(0, 0);
        float v = __int_as_float(ev.y);
        uint2 r = *reinterpret_cast<const uint2*>(xq + (size_t)ev.x * DIM);
        float2 f0 = __half22float2(*reinterpret_cast<__half2*>(&r.x));
        float2 f1 = __half22float2(*reinterpret_cast<__half2*>(&r.y));
        acc.x = fmaf(v, f0.x, acc.x);
        acc.y = fmaf(v, f0.y, acc.y);
        acc.z = fmaf(v, f1.x, acc.z);
        acc.w = fmaf(v, f1.y, acc.w);
    }

    // merge the two half-warp partial sums (4 shfls per ROW, not per edge)
    acc.x += __shfl_xor_sync(0xffffffffu, acc.x, 16);
    acc.y += __shfl_xor_sync(0xffffffffu, acc.y, 16);
    acc.z += __shfl_xor_sync(0xffffffffu, acc.z, 16);
    acc.w += __shfl_xor_sync(0xffffffffu, acc.w, 16);

    if (lane < 16) {
        __half2 a = __floats2half2_rn(acc.x, acc.y);
        __half2 b = __floats2half2_rn(acc.z, acc.w);
        uint2 pk;
        pk.x = *reinterpret_cast<unsigned*>(&a);
        pk.y = *reinterpret_cast<unsigned*>(&b);
        *reinterpret_cast<uint2*>(&yout[(size_t)gw * DIM + q * 4]) = pk;
    }
}

// ---------------- final combine: out = emb + y1/2 + y2/3 + y3/4 ---------------
__global__ void k_combine(const float* __restrict__ emb, float* __restrict__ out) {
    int i = blockIdx.x * blockDim.x + threadIdx.x;
    const int total4 = (NN * DIM) / 4;
    if (i >= total4) return;

    float4 ef = *reinterpret_cast<const float4*>(&emb[(size_t)i * 4]);
    uint2 a = *reinterpret_cast<const uint2*>(&g_h1[(size_t)i * 4]);
    uint2 b = *reinterpret_cast<const uint2*>(&g_h2[(size_t)i * 4]);
    uint2 c = *reinterpret_cast<const uint2*>(&g_h3[(size_t)i * 4]);

    float2 a0 = __half22float2(*reinterpret_cast<__half2*>(&a.x));
    float2 a1 = __half22float2(*reinterpret_cast<__half2*>(&a.y));
    float2 b0 = __half22float2(*reinterpret_cast<__half2*>(&b.x));
    float2 b1 = __half22float2(*reinterpret_cast<__half2*>(&b.y));
    float2 c0 = __half22float2(*reinterpret_cast<__half2*>(&c.x));
    float2 c1 = __half22float2(*reinterpret_cast<__half2*>(&c.y));

    const float w1 = 1.0f / 2.0f, w2 = 1.0f / 3.0f, w3 = 1.0f / 4.0f;
    ef.x = ef.x + w1 * a0.x + w2 * b0.x + w3 * c0.x;
    ef.y = ef.y + w1 * a0.y + w2 * b0.y + w3 * c0.y;
    ef.z = ef.z + w1 * a1.x + w2 * b1.x + w3 * c1.x;
    ef.w = ef.w + w1 * a1.y + w2 * b1.y + w3 * c1.y;

    *reinterpret_cast<float4*>(&out[(size_t)i * 4]) = ef;
}

// ---------------- launch ------------------------------------------------------
extern "C" void kernel_launch(void* const* d_in, const int* in_sizes, int n_in,
                              void* d_out, int out_size) {
    const int*   rows = (const int*)d_in[0];
    const int*   cols = (const int*)d_in[1];
    const float* vals = (const float*)d_in[2];
    const float* emb  = (const float*)d_in[3];
    float*       out  = (float*)d_out;

    (void)in_sizes; (void)n_in; (void)out_size;

    static __half* h0 = nullptr;
    static __half* h1 = nullptr;
    static __half* h2 = nullptr;
    static __half* h3 = nullptr;
    if (!h0) {
        void* p;
        cudaGetSymbolAddress(&p, g_h0); h0 = (__half*)p;
        cudaGetSymbolAddress(&p, g_h1); h1 = (__half*)p;
        cudaGetSymbolAddress(&p, g_h2); h2 = (__half*)p;
        cudaGetSymbolAddress(&p, g_h3); h3 = (__half*)p;
    }

    // ---- CSR build + emb conversion ----
    k_conv_zero<<<2048, 256>>>(emb);
    k_hist<<<1280, 256>>>((const int4*)rows);
    k_chunksum<<<NB, 256>>>();
    k_scan_bsum<<<1, 256>>>();
    k_writeptr<<<NB, 1024>>>();
    k_scatter<<<1280, 256>>>((const int4*)rows, (const int4*)cols,
                             (const float4*)vals);

    // ---- 3 SpMM layers ----
    const int threads = 256;
    const int blocks  = (NN * 32 + threads - 1) / threads;  // warp per row

    k_spmm<<<blocks, threads>>>(h0, h1);   // y1 = A @ emb
    k_spmm<<<blocks, threads>>>(h1, h2);   // y2 = A @ y1
    k_spmm<<<blocks, threads>>>(h2, h3);   // y3 = A @ y2

    // ---- out = emb + y1/2 + y2/3 + y3/4 ----
    const int total4 = (NN * DIM) / 4;
    k_combine<<<(total4 + 255) / 256, 256>>>(emb, out);
}